// round 2
// baseline (speedup 1.0000x reference)
#include <cuda_runtime.h>

// FlexQMixer — closed-form reduction.
//
// The reference's attention-mask logic is degenerate: agent_mask and
// entity_mask are all-ones, so `m = attn_mask > 0.5` is all-True, attention
// weights are zeroed by the fully_masked branch, and BOTH post-projection
// `where(agent_mask > 0.5, 0, ·)` guards zero the hypernet outputs entirely.
// Hence hn(i) == 0 for all i, w1 == 1/32, b1 == 0, w_final == 1/32, v == 0,
// and the whole mixer collapses exactly to:
//
//     out[b,t] = elu( (sum_{a=0..7} agent_qs[b,t,a]) / 32 )
//
// 32768 outputs, 1 MB input read, 128 KB write — launch-overhead-bound.
// state and all 8 weight tensors are dead inputs.

__global__ void __launch_bounds__(128)
flexqmixer_kernel(const float* __restrict__ qs, float* __restrict__ out, int n) {
    const int stride = gridDim.x * blockDim.x;
    for (int i = blockIdx.x * blockDim.x + threadIdx.x; i < n; i += stride) {
        // 8 consecutive floats per output, 32B-aligned -> two float4 loads.
        const float4* p = reinterpret_cast<const float4*>(qs) + (size_t)i * 2;
        float4 a = p[0];
        float4 b = p[1];
        float s = ((a.x + a.y) + (a.z + a.w)) + ((b.x + b.y) + (b.z + b.w));
        s *= 0.03125f;  // 1/32
        out[i] = (s > 0.0f) ? s : (expf(s) - 1.0f);  // elu, alpha=1
    }
}

extern "C" void kernel_launch(void* const* d_in, const int* in_sizes, int n_in,
                              void* d_out, int out_size) {
    const float* agent_qs = (const float*)d_in[0];  // (128, 256, 8) f32
    float* out = (float*)d_out;                     // (128, 256, 1) f32
    int n = out_size;                               // 32768
    // 128 blocks x 128 threads = 16384 threads, 2 outputs each (grid-stride):
    // 4 independent LDG.128 in flight per thread, small fixed grid.
    flexqmixer_kernel<<<128, 128>>>(agent_qs, out, n);
}

// round 5
// speedup vs baseline: 1.0632x; 1.0632x over previous
#include <cuda_runtime.h>

// FlexQMixer — closed-form reduction.
//
// The reference's attention-mask logic is degenerate: agent_mask and
// entity_mask are all-ones, so `m = attn_mask > 0.5` is all-True, attention
// weights are zeroed by the fully_masked branch, and BOTH post-projection
// `where(agent_mask > 0.5, 0, ·)` guards zero the hypernet outputs entirely.
// Hence hn(i) == 0 for all i, w1 == 1/32, b1 == 0, w_final == 1/32, v == 0,
// and the whole mixer collapses exactly to:
//
//     out[b,t] = elu( (sum_{a=0..7} agent_qs[b,t,a]) / 32 )
//
// 32768 outputs, 1 MB read + 128 KB write. R2 showed this is latency-bound
// (occ 5.6%, DRAM 2.7%): shape for ONE memory round — one output per thread,
// both LDG.128 front-batched, no grid-stride loop.

__global__ void __launch_bounds__(256)
flexqmixer_kernel(const float* __restrict__ qs, float* __restrict__ out, int n) {
    int i = blockIdx.x * blockDim.x + threadIdx.x;
    if (i >= n) return;
    const float4* p = reinterpret_cast<const float4*>(qs) + (size_t)i * 2;
    // Two independent 16B loads, issued back-to-back (MLP=2 per thread,
    // 1024 warps chip-wide -> latency fully overlapped across warps).
    float4 a = p[0];
    float4 b = p[1];
    float s = ((a.x + a.y) + (a.z + a.w)) + ((b.x + b.y) + (b.z + b.w));
    s *= 0.03125f;  // 1/32
    out[i] = (s > 0.0f) ? s : (expf(s) - 1.0f);  // elu, alpha=1
}

extern "C" void kernel_launch(void* const* d_in, const int* in_sizes, int n_in,
                              void* d_out, int out_size) {
    const float* agent_qs = (const float*)d_in[0];  // (128, 256, 8) f32
    float* out = (float*)d_out;                     // (128, 256, 1) f32
    int n = out_size;                               // 32768
    int threads = 256;
    int blocks = (n + threads - 1) / threads;       // 128 blocks, single wave
    flexqmixer_kernel<<<blocks, threads>>>(agent_qs, out, n);
}